// round 10
// baseline (speedup 1.0000x reference)
#include <cuda_runtime.h>
#include <cstdint>

#define SCALE_F 0.17677669529663687f

typedef unsigned long long u64;

__device__ __forceinline__ u64 pk2(float lo, float hi) {
    u64 r; asm("mov.b64 %0,{%1,%2};" : "=l"(r) : "f"(lo), "f"(hi)); return r;
}
__device__ __forceinline__ u64 bcast2(float v) { return pk2(v, v); }
__device__ __forceinline__ void upk2(u64 v, float &lo, float &hi) {
    asm("mov.b64 {%0,%1},%2;" : "=f"(lo), "=f"(hi) : "l"(v));
}
__device__ __forceinline__ u64 ffma2(u64 a, u64 b, u64 c) {
    u64 d; asm("fma.rn.f32x2 %0,%1,%2,%3;" : "=l"(d) : "l"(a), "l"(b), "l"(c)); return d;
}

// ---------------- scratch ----------------
__device__ float g_q[2097152];        // [B,H,N,D]
__device__ float g_k[2097152];
__device__ float g_v[2097152];
__device__ float g_attn[33554432];    // [B,H,N,N]
__device__ float g_invden[65536];     // [B*H*N]
__device__ float g_node1[2097152];    // [B,N,C]
__device__ float g_wred[262144];      // [B,N,E]

// ---------------- generic 128x128 SGEMM: out = A @ W^T (+bias), FFMA2 ----------------
template<int EPI>
__global__ __launch_bounds__(256)
void sgemm_kernel(const float* __restrict__ A, const float* __restrict__ W,
                  const float* __restrict__ bias, float* __restrict__ Cout, int K)
{
    __shared__ float As[8][128];
    __shared__ float Ws[8][128];
    const int tid = threadIdx.x;
    const int bm = blockIdx.y << 7;
    const int bn = blockIdx.x << 7;
    const int lr = tid >> 1;
    const int lc = (tid & 1) << 2;
    const int tm = (tid >> 4) << 3;
    const int tn = (tid & 15) << 3;

    const float* Ab = (EPI == 1) ? (const float*)g_wred
                    : (EPI == 2) ? (const float*)g_node1 : A;

    u64 acc[4][8];
#pragma unroll
    for (int p = 0; p < 4; p++)
#pragma unroll
        for (int j = 0; j < 8; j++) acc[p][j] = 0ull;

    const float* Ap = Ab + (size_t)(bm + lr) * K + lc;
    const float* Wp = W  + (size_t)(bn + lr) * K + lc;

    for (int k0 = 0; k0 < K; k0 += 8) {
        float4 av = *(const float4*)(Ap + k0);
        float4 wv = *(const float4*)(Wp + k0);
        As[lc + 0][lr] = av.x; As[lc + 1][lr] = av.y;
        As[lc + 2][lr] = av.z; As[lc + 3][lr] = av.w;
        Ws[lc + 0][lr] = wv.x; Ws[lc + 1][lr] = wv.y;
        Ws[lc + 2][lr] = wv.z; Ws[lc + 3][lr] = wv.w;
        __syncthreads();
#pragma unroll
        for (int kk = 0; kk < 8; kk++) {
            ulonglong2 a01 = *(const ulonglong2*)&As[kk][tm];
            ulonglong2 a23 = *(const ulonglong2*)&As[kk][tm + 4];
            u64 ap[4] = {a01.x, a01.y, a23.x, a23.y};
            float4 t2 = *(const float4*)&Ws[kk][tn];
            float4 t3 = *(const float4*)&Ws[kk][tn + 4];
            u64 bb[8];
            bb[0] = bcast2(t2.x); bb[1] = bcast2(t2.y);
            bb[2] = bcast2(t2.z); bb[3] = bcast2(t2.w);
            bb[4] = bcast2(t3.x); bb[5] = bcast2(t3.y);
            bb[6] = bcast2(t3.z); bb[7] = bcast2(t3.w);
#pragma unroll
            for (int p = 0; p < 4; p++)
#pragma unroll
                for (int j = 0; j < 8; j++)
                    acc[p][j] = ffma2(ap[p], bb[j], acc[p][j]);
        }
        __syncthreads();
    }

    const int col0 = bn + tn;
    float4 bv0 = *(const float4*)&bias[col0];
    float4 bv1 = *(const float4*)&bias[col0 + 4];

#pragma unroll
    for (int p = 0; p < 4; p++) {
        float v2[2][8];
#pragma unroll
        for (int j = 0; j < 8; j++) upk2(acc[p][j], v2[0][j], v2[1][j]);
#pragma unroll
        for (int rr = 0; rr < 2; rr++) {
            const int row = bm + tm + 2 * p + rr;
            float4 o0, o1;
            o0.x = v2[rr][0] + bv0.x; o0.y = v2[rr][1] + bv0.y;
            o0.z = v2[rr][2] + bv0.z; o0.w = v2[rr][3] + bv0.w;
            o1.x = v2[rr][4] + bv1.x; o1.y = v2[rr][5] + bv1.y;
            o1.z = v2[rr][6] + bv1.z; o1.w = v2[rr][7] + bv1.w;
            if (EPI == 0) {
                int s  = col0 >> 9;
                int hd = col0 & 511;
                float* base = (s == 0 ? g_q : (s == 1 ? g_k : g_v));
                int b_ = row >> 9, n = row & 511;
                float* dst = base + ((size_t)((b_ << 4) + (hd >> 5)) << 14) + (n << 5) + (hd & 31);
                *(float4*)dst = o0; *(float4*)(dst + 4) = o1;
            } else {
                float* Cb = (EPI == 1) ? (float*)g_node1 : Cout;
                float* dst = Cb + ((size_t)row << 9) + col0;
                if (EPI == 1) {
                    float4 c0 = *(const float4*)dst;
                    float4 c1 = *(const float4*)(dst + 4);
                    o0.x += c0.x; o0.y += c0.y; o0.z += c0.z; o0.w += c0.w;
                    o1.x += c1.x; o1.y += c1.y; o1.z += c1.z; o1.w += c1.w;
                }
                *(float4*)dst = o0; *(float4*)(dst + 4) = o1;
            }
        }
    }
}

// ---------------- attn = sum_e edge[b,e,n,m]*rw[h,e] + rb[h]; 2 n per block ----------------
__global__ __launch_bounds__(256)
void bias_kernel(const float* __restrict__ edge, const float* __restrict__ rw,
                 const float* __restrict__ rb)
{
    __shared__ u64 rwP[64][16];     // [e][h] pre-broadcast pairs
    __shared__ float s_rb[16];
    const int tid = threadIdx.x;
    const int n = (blockIdx.x << 1) + (tid >> 7), b = blockIdx.y;
    const int tid2 = tid & 127;
    for (int i = tid; i < 1024; i += 256) { int h = i >> 6, e = i & 63; rwP[e][h] = bcast2(rw[i]); }
    if (tid < 16) s_rb[tid] = rb[tid];
    __syncthreads();

    const int m0 = tid2 << 2;
    u64 acc[16][2];
#pragma unroll
    for (int h = 0; h < 16; h++) { acc[h][0] = 0ull; acc[h][1] = 0ull; }

    const float* ep = edge + (size_t)b * 16777216 + (size_t)n * 512 + m0;
#pragma unroll 4
    for (int e = 0; e < 64; e++) {
        ulonglong2 v = *(const ulonglong2*)(ep + (size_t)e * 262144);
#pragma unroll
        for (int h = 0; h < 16; h += 2) {
            ulonglong2 w2 = *(const ulonglong2*)&rwP[e][h];
            acc[h][0]   = ffma2(w2.x, v.x, acc[h][0]);
            acc[h][1]   = ffma2(w2.x, v.y, acc[h][1]);
            acc[h+1][0] = ffma2(w2.y, v.x, acc[h+1][0]);
            acc[h+1][1] = ffma2(w2.y, v.y, acc[h+1][1]);
        }
    }
    float* op = g_attn + (size_t)b * 4194304 + (size_t)n * 512 + m0;
#pragma unroll
    for (int h = 0; h < 16; h++) {
        float rv = s_rb[h];
        float4 o;
        upk2(acc[h][0], o.x, o.y);
        upk2(acc[h][1], o.z, o.w);
        o.x += rv; o.y += rv; o.z += rv; o.w += rv;
        *(float4*)(op + (size_t)h * 262144) = o;
    }
}

// ---------------- attn += SCALE * q@k^T, per (b,h), 64x64 tiles ----------------
__global__ __launch_bounds__(256)
void scores_kernel()
{
    __shared__ float Qs[32][68];   // [d][n]
    __shared__ float Ks[32][68];   // [d][m]
    const int tid = threadIdx.x;
    const int bh = blockIdx.z;
    const int n0 = blockIdx.y << 6;
    const int m0 = blockIdx.x << 6;
    const float* qp = g_q + (size_t)bh * 16384;
    const float* kp = g_k + (size_t)bh * 16384;

    const int r = tid >> 2;
    const int c = (tid & 3) << 3;
    {
        float4 q1 = *(const float4*)(qp + (size_t)(n0 + r) * 32 + c);
        float4 q2 = *(const float4*)(qp + (size_t)(n0 + r) * 32 + c + 4);
        Qs[c+0][r]=q1.x; Qs[c+1][r]=q1.y; Qs[c+2][r]=q1.z; Qs[c+3][r]=q1.w;
        Qs[c+4][r]=q2.x; Qs[c+5][r]=q2.y; Qs[c+6][r]=q2.z; Qs[c+7][r]=q2.w;
        float4 k1 = *(const float4*)(kp + (size_t)(m0 + r) * 32 + c);
        float4 k2 = *(const float4*)(kp + (size_t)(m0 + r) * 32 + c + 4);
        Ks[c+0][r]=k1.x; Ks[c+1][r]=k1.y; Ks[c+2][r]=k1.z; Ks[c+3][r]=k1.w;
        Ks[c+4][r]=k2.x; Ks[c+5][r]=k2.y; Ks[c+6][r]=k2.z; Ks[c+7][r]=k2.w;
    }
    __syncthreads();

    const int tn = (tid >> 4) << 2;
    const int tm = (tid & 15) << 2;
    u64 acc[2][4];
#pragma unroll
    for (int p = 0; p < 2; p++)
#pragma unroll
        for (int j = 0; j < 4; j++) acc[p][j] = 0ull;

#pragma unroll
    for (int d = 0; d < 32; d++) {
        ulonglong2 av = *(const ulonglong2*)&Qs[d][tn];
        float4 bf = *(const float4*)&Ks[d][tm];
        u64 bb[4] = {bcast2(bf.x), bcast2(bf.y), bcast2(bf.z), bcast2(bf.w)};
        u64 ap[2] = {av.x, av.y};
#pragma unroll
        for (int p = 0; p < 2; p++)
#pragma unroll
            for (int j = 0; j < 4; j++)
                acc[p][j] = ffma2(ap[p], bb[j], acc[p][j]);
    }

#pragma unroll
    for (int p = 0; p < 2; p++) {
        float lo[4], hi[4];
#pragma unroll
        for (int j = 0; j < 4; j++) upk2(acc[p][j], lo[j], hi[j]);
#pragma unroll
        for (int rr = 0; rr < 2; rr++) {
            const float* src = rr ? hi : lo;
            float* op = g_attn + ((size_t)bh * 512 + n0 + tn + 2 * p + rr) * 512 + m0 + tm;
            float4 cur = *(float4*)op;
            cur.x += SCALE_F * src[0];
            cur.y += SCALE_F * src[1];
            cur.z += SCALE_F * src[2];
            cur.w += SCALE_F * src[3];
            *(float4*)op = cur;
        }
    }
}

// ---------------- edge path: stats + t=a+attn + expand GEMM (4e/thread) + edge softmax ----------------
__global__ __launch_bounds__(256)
void edge_kernel(const unsigned char* __restrict__ mask,
                 const float* __restrict__ ew, const float* __restrict__ eb,
                 float* __restrict__ out_edge)
{
    __shared__ float t_s[16][520];
    __shared__ u64 ewP[16][64];      // [h][e] pre-broadcast pairs
    __shared__ float eb_s[64];
    __shared__ float L_s[16];
    __shared__ unsigned char mk[512];
    const int tid = threadIdx.x;
    const int n = blockIdx.x, b = blockIdx.y;
    const int lane = tid & 31, w = tid >> 5;

    for (int i = tid; i < 1024; i += 256) { int e = i >> 4, h = i & 15; ewP[h][e] = bcast2(ew[i]); }
    if (tid < 64) eb_s[tid] = eb[tid];
    mk[tid] = mask[(b << 9) + tid];
    mk[tid + 256] = mask[(b << 9) + tid + 256];

    // phase 0: load raw attn rows for this n
    const float* ap = g_attn + (size_t)b * 4194304 + (size_t)n * 512;
#pragma unroll
    for (int rep = 0; rep < 2; rep++) {
        const int mm = tid + (rep << 8);
#pragma unroll
        for (int h = 0; h < 16; h++)
            t_s[h][mm] = ap[(size_t)h * 262144 + mm];
    }
    __syncthreads();

    // phase 0b: row sums of exp (no max needed) -> L = 1/sum; warp w handles h=2w,2w+1
#pragma unroll
    for (int hh = 0; hh < 2; hh++) {
        const int h = (w << 1) + hh;
        float s = 0.f;
#pragma unroll
        for (int j = 0; j < 4; j++) {
            const int m = (lane << 2) + (j << 7);
            float4 x = *(const float4*)&t_s[h][m];
            uchar4 m4 = *(const uchar4*)&mk[m];
            if (!m4.x) s += __expf(x.x);
            if (!m4.y) s += __expf(x.y);
            if (!m4.z) s += __expf(x.z);
            if (!m4.w) s += __expf(x.w);
        }
#pragma unroll
        for (int off = 16; off > 0; off >>= 1)
            s += __shfl_xor_sync(0xffffffffu, s, off);
        if (lane == 0) {
            float inv = 1.0f / s;
            L_s[h] = inv;
            g_invden[(b * 16 + h) * 512 + n] = inv;
        }
    }
    __syncthreads();

    // phase 1: t = a + x in place
#pragma unroll
    for (int rep = 0; rep < 2; rep++) {
        const int mm = tid + (rep << 8);
        const bool k = mk[mm] != 0;
#pragma unroll
        for (int h = 0; h < 16; h++) {
            float x = t_s[h][mm];
            float a = k ? 0.f : __expf(x) * L_s[h];
            t_s[h][mm] = a + x;
        }
    }
    __syncthreads();

    // phase 2: 4 e per thread (16 e-groups x 16 m-groups), weights from broadcast smem
    const int eg = tid >> 4;          // 0..15
    const int mg = tid & 15;          // 0..15
    const int e0 = eg << 2;
    u64 bep[4];
#pragma unroll
    for (int e = 0; e < 4; e++) bep[e] = bcast2(eb_s[e0 + e]);
    float* gbase = out_edge + (size_t)(b * 64 + e0) * 262144 + (size_t)n * 512;

    float S1[4] = {0.f, 0.f, 0.f, 0.f}, S2[4] = {0.f, 0.f, 0.f, 0.f};
#pragma unroll 2
    for (int j = 0; j < 8; j++) {
        const int m0 = (mg << 2) + (j << 6);
        u64 o[4][2];
#pragma unroll
        for (int e = 0; e < 4; e++) { o[e][0] = bep[e]; o[e][1] = bep[e]; }
#pragma unroll
        for (int h = 0; h < 16; h++) {
            ulonglong2 tv = *(const ulonglong2*)&t_s[h][m0];
            ulonglong2 w01 = *(const ulonglong2*)&ewP[h][e0];
            ulonglong2 w23 = *(const ulonglong2*)&ewP[h][e0 + 2];
            o[0][0] = ffma2(w01.x, tv.x, o[0][0]); o[0][1] = ffma2(w01.x, tv.y, o[0][1]);
            o[1][0] = ffma2(w01.y, tv.x, o[1][0]); o[1][1] = ffma2(w01.y, tv.y, o[1][1]);
            o[2][0] = ffma2(w23.x, tv.x, o[2][0]); o[2][1] = ffma2(w23.x, tv.y, o[2][1]);
            o[3][0] = ffma2(w23.y, tv.x, o[3][0]); o[3][1] = ffma2(w23.y, tv.y, o[3][1]);
        }
        uchar4 m4 = *(const uchar4*)&mk[m0];
        unsigned char mc[4] = {m4.x, m4.y, m4.z, m4.w};
#pragma unroll
        for (int e = 0; e < 4; e++) {
            ulonglong2 st; st.x = o[e][0]; st.y = o[e][1];
            *(ulonglong2*)(gbase + (size_t)e * 262144 + m0) = st;
            float f[4];
            upk2(o[e][0], f[0], f[1]);
            upk2(o[e][1], f[2], f[3]);
#pragma unroll
            for (int c = 0; c < 4; c++) {
                float ev = mc[c] ? 0.f : __expf(f[c]);
                S1[e] += ev;
                S2[e] = fmaf(ev, f[c], S2[e]);
            }
        }
    }
#pragma unroll
    for (int off = 1; off < 16; off <<= 1) {
#pragma unroll
        for (int e = 0; e < 4; e++) {
            S1[e] += __shfl_xor_sync(0xffffffffu, S1[e], off);
            S2[e] += __shfl_xor_sync(0xffffffffu, S2[e], off);
        }
    }
    if (mg == 0) {
        float* wr = g_wred + ((size_t)b * 512 + n) * 64 + e0;
#pragma unroll
        for (int e = 0; e < 4; e++) wr[e] = S2[e] / S1[e];
    }
}

// ---------------- node1 = a @ v per (b,h), FFMA2, no-max softmax ----------------
__global__ __launch_bounds__(256)
void node_kernel(const unsigned char* __restrict__ mask)
{
    __shared__ float a_s[64][68];
    __shared__ float v_s[64][33];
    __shared__ float Is[64];
    __shared__ unsigned char mk[512];
    const int tid = threadIdx.x;
    const int n0 = blockIdx.x << 6, h = blockIdx.y, b = blockIdx.z;
    const int bh = b * 16 + h;
    const float* ap = g_attn + (size_t)bh * 262144;
    const float* vp = g_v + (size_t)bh * 16384;
    const int d = tid & 31, nn = tid >> 5;

    if (tid < 64) Is[tid] = g_invden[bh * 512 + n0 + tid];
    for (int i = tid; i < 512; i += 256) mk[i] = mask[(b << 9) + i];
    __syncthreads();

    u64 acc2[8];
#pragma unroll
    for (int i = 0; i < 8; i++) acc2[i] = 0ull;

    for (int m0 = 0; m0 < 512; m0 += 64) {
        for (int i = tid; i < 1024; i += 256) {
            int r = i >> 4, c4 = (i & 15) << 2;
            float4 x = *(const float4*)(ap + (size_t)(n0 + r) * 512 + m0 + c4);
            float I = Is[r];
            a_s[r][c4+0] = mk[m0+c4+0] ? 0.f : __expf(x.x) * I;
            a_s[r][c4+1] = mk[m0+c4+1] ? 0.f : __expf(x.y) * I;
            a_s[r][c4+2] = mk[m0+c4+2] ? 0.f : __expf(x.z) * I;
            a_s[r][c4+3] = mk[m0+c4+3] ? 0.f : __expf(x.w) * I;
        }
        for (int i = tid; i < 512; i += 256) {
            int r = i >> 3, c4 = (i & 7) << 2;
            float4 x = *(const float4*)(vp + (size_t)(m0 + r) * 32 + c4);
            v_s[r][c4] = x.x; v_s[r][c4+1] = x.y; v_s[r][c4+2] = x.z; v_s[r][c4+3] = x.w;
        }
        __syncthreads();
#pragma unroll 4
        for (int m = 0; m < 64; m += 4) {
            u64 vp0 = pk2(v_s[m][d],   v_s[m+1][d]);
            u64 vp1 = pk2(v_s[m+2][d], v_s[m+3][d]);
#pragma unroll
            for (int i = 0; i < 8; i++) {
                ulonglong2 a2 = *(const ulonglong2*)&a_s[(nn << 3) + i][m];
                acc2[i] = ffma2(a2.x, vp0, acc2[i]);
                acc2[i] = ffma2(a2.y, vp1, acc2[i]);
            }
        }
        __syncthreads();
    }
    float* op = g_node1 + (size_t)(b * 512 + n0 + (nn << 3)) * 512 + h * 32 + d;
#pragma unroll
    for (int i = 0; i < 8; i++) {
        float lo, hi;
        upk2(acc2[i], lo, hi);
        op[(size_t)i * 512] = lo + hi;
    }
}

extern "C" void kernel_launch(void* const* d_in, const int* in_sizes, int n_in,
                              void* d_out, int out_size)
{
    const float* node_embeds = (const float*)d_in[0];
    const float* edge_embeds = (const float*)d_in[1];
    const unsigned char* padding_mask = (const unsigned char*)d_in[2];
    const float* qkv_w = (const float*)d_in[3];
    const float* qkv_b = (const float*)d_in[4];
    const float* reduce_w = (const float*)d_in[5];
    const float* reduce_b = (const float*)d_in[6];
    const float* expand_w = (const float*)d_in[7];
    const float* expand_b = (const float*)d_in[8];
    const float* fc_w = (const float*)d_in[9];
    const float* fc_b = (const float*)d_in[10];
    const float* proj_w = (const float*)d_in[11];
    const float* proj_b = (const float*)d_in[12];
    float* out = (float*)d_out;
    float* out_node = out;                 // [8,512,512]
    float* out_edge = out + 2097152;       // [8,64,512,512]

    sgemm_kernel<0><<<dim3(12, 32), 256>>>(node_embeds, qkv_w, qkv_b, nullptr, 512);
    bias_kernel<<<dim3(256, 8), 256>>>(edge_embeds, reduce_w, reduce_b);
    scores_kernel<<<dim3(8, 8, 128), 256>>>();
    edge_kernel<<<dim3(512, 8), 256>>>(padding_mask, expand_w, expand_b, out_edge);
    node_kernel<<<dim3(8, 16, 8), 256>>>(padding_mask);
    sgemm_kernel<1><<<dim3(4, 32), 256>>>(nullptr, fc_w, fc_b, nullptr, 64);
    sgemm_kernel<2><<<dim3(4, 32), 256>>>(nullptr, proj_w, proj_b, out_node, 512);
}

// round 12
// speedup vs baseline: 1.2285x; 1.2285x over previous
#include <cuda_runtime.h>
#include <cstdint>

#define SCALE_F 0.17677669529663687f

typedef unsigned long long u64;

__device__ __forceinline__ u64 pk2(float lo, float hi) {
    u64 r; asm("mov.b64 %0,{%1,%2};" : "=l"(r) : "f"(lo), "f"(hi)); return r;
}
__device__ __forceinline__ u64 bcast2(float v) { return pk2(v, v); }
__device__ __forceinline__ void upk2(u64 v, float &lo, float &hi) {
    asm("mov.b64 {%0,%1},%2;" : "=f"(lo), "=f"(hi) : "l"(v));
}
__device__ __forceinline__ u64 ffma2(u64 a, u64 b, u64 c) {
    u64 d; asm("fma.rn.f32x2 %0,%1,%2,%3;" : "=l"(d) : "l"(a), "l"(b), "l"(c)); return d;
}

// ---------------- scratch ----------------
__device__ float g_q[2097152];        // [B,H,N,D]
__device__ float g_k[2097152];
__device__ float g_v[2097152];
__device__ float g_attn[33554432];    // [B,H,N,N]
__device__ float g_invden[65536];     // [B*H*N]
__device__ float g_node1[2097152];    // [B,N,C]
__device__ float g_wred[262144];      // [B,N,E]

// ---------------- generic 128x128 SGEMM: out = A @ W^T (+bias), FFMA2 ----------------
template<int EPI>
__global__ __launch_bounds__(256)
void sgemm_kernel(const float* __restrict__ A, const float* __restrict__ W,
                  const float* __restrict__ bias, float* __restrict__ Cout, int K)
{
    __shared__ float As[8][128];
    __shared__ float Ws[8][128];
    const int tid = threadIdx.x;
    const int bm = blockIdx.y << 7;
    const int bn = blockIdx.x << 7;
    const int lr = tid >> 1;
    const int lc = (tid & 1) << 2;
    const int tm = (tid >> 4) << 3;
    const int tn = (tid & 15) << 3;

    const float* Ab = (EPI == 1) ? (const float*)g_wred
                    : (EPI == 2) ? (const float*)g_node1 : A;

    u64 acc[4][8];
#pragma unroll
    for (int p = 0; p < 4; p++)
#pragma unroll
        for (int j = 0; j < 8; j++) acc[p][j] = 0ull;

    const float* Ap = Ab + (size_t)(bm + lr) * K + lc;
    const float* Wp = W  + (size_t)(bn + lr) * K + lc;

    for (int k0 = 0; k0 < K; k0 += 8) {
        float4 av = *(const float4*)(Ap + k0);
        float4 wv = *(const float4*)(Wp + k0);
        As[lc + 0][lr] = av.x; As[lc + 1][lr] = av.y;
        As[lc + 2][lr] = av.z; As[lc + 3][lr] = av.w;
        Ws[lc + 0][lr] = wv.x; Ws[lc + 1][lr] = wv.y;
        Ws[lc + 2][lr] = wv.z; Ws[lc + 3][lr] = wv.w;
        __syncthreads();
#pragma unroll
        for (int kk = 0; kk < 8; kk++) {
            ulonglong2 a01 = *(const ulonglong2*)&As[kk][tm];
            ulonglong2 a23 = *(const ulonglong2*)&As[kk][tm + 4];
            u64 ap[4] = {a01.x, a01.y, a23.x, a23.y};
            float4 t2 = *(const float4*)&Ws[kk][tn];
            float4 t3 = *(const float4*)&Ws[kk][tn + 4];
            u64 bb[8];
            bb[0] = bcast2(t2.x); bb[1] = bcast2(t2.y);
            bb[2] = bcast2(t2.z); bb[3] = bcast2(t2.w);
            bb[4] = bcast2(t3.x); bb[5] = bcast2(t3.y);
            bb[6] = bcast2(t3.z); bb[7] = bcast2(t3.w);
#pragma unroll
            for (int p = 0; p < 4; p++)
#pragma unroll
                for (int j = 0; j < 8; j++)
                    acc[p][j] = ffma2(ap[p], bb[j], acc[p][j]);
        }
        __syncthreads();
    }

    const int col0 = bn + tn;
    float4 bv0 = *(const float4*)&bias[col0];
    float4 bv1 = *(const float4*)&bias[col0 + 4];

#pragma unroll
    for (int p = 0; p < 4; p++) {
        float v2[2][8];
#pragma unroll
        for (int j = 0; j < 8; j++) upk2(acc[p][j], v2[0][j], v2[1][j]);
#pragma unroll
        for (int rr = 0; rr < 2; rr++) {
            const int row = bm + tm + 2 * p + rr;
            float4 o0, o1;
            o0.x = v2[rr][0] + bv0.x; o0.y = v2[rr][1] + bv0.y;
            o0.z = v2[rr][2] + bv0.z; o0.w = v2[rr][3] + bv0.w;
            o1.x = v2[rr][4] + bv1.x; o1.y = v2[rr][5] + bv1.y;
            o1.z = v2[rr][6] + bv1.z; o1.w = v2[rr][7] + bv1.w;
            if (EPI == 0) {
                int s  = col0 >> 9;
                int hd = col0 & 511;
                float* base = (s == 0 ? g_q : (s == 1 ? g_k : g_v));
                int b_ = row >> 9, n = row & 511;
                float* dst = base + ((size_t)((b_ << 4) + (hd >> 5)) << 14) + (n << 5) + (hd & 31);
                *(float4*)dst = o0; *(float4*)(dst + 4) = o1;
            } else {
                float* Cb = (EPI == 1) ? (float*)g_node1 : Cout;
                float* dst = Cb + ((size_t)row << 9) + col0;
                if (EPI == 1) {
                    float4 c0 = *(const float4*)dst;
                    float4 c1 = *(const float4*)(dst + 4);
                    o0.x += c0.x; o0.y += c0.y; o0.z += c0.z; o0.w += c0.w;
                    o1.x += c1.x; o1.y += c1.y; o1.z += c1.z; o1.w += c1.w;
                }
                *(float4*)dst = o0; *(float4*)(dst + 4) = o1;
            }
        }
    }
}

// ---------------- attn = sum_e edge[b,e,n,m]*rw[h,e] + rb[h] (FFMA2, float4 w) ----------------
__global__ __launch_bounds__(128)
void bias_kernel(const float* __restrict__ edge, const float* __restrict__ rw,
                 const float* __restrict__ rb)
{
    __shared__ float rwT[64][16];   // [e][h], broadcast reads
    __shared__ float s_rb[16];
    const int tid = threadIdx.x;
    const int n = blockIdx.x, b = blockIdx.y;
    for (int i = tid; i < 1024; i += 128) { int h = i >> 6, e = i & 63; rwT[e][h] = rw[i]; }
    if (tid < 16) s_rb[tid] = rb[tid];
    __syncthreads();

    const int m0 = tid << 2;
    u64 acc[16][2];
#pragma unroll
    for (int h = 0; h < 16; h++) { acc[h][0] = 0ull; acc[h][1] = 0ull; }

    const float* ep = edge + (size_t)b * 16777216 + (size_t)n * 512 + m0;
#pragma unroll 4
    for (int e = 0; e < 64; e++) {
        ulonglong2 v = *(const ulonglong2*)(ep + (size_t)e * 262144);
        float4 w0 = *(const float4*)&rwT[e][0];
        float4 w1 = *(const float4*)&rwT[e][4];
        float4 w2 = *(const float4*)&rwT[e][8];
        float4 w3 = *(const float4*)&rwT[e][12];
        float wf[16] = {w0.x,w0.y,w0.z,w0.w, w1.x,w1.y,w1.z,w1.w,
                        w2.x,w2.y,w2.z,w2.w, w3.x,w3.y,w3.z,w3.w};
#pragma unroll
        for (int h = 0; h < 16; h++) {
            u64 w = bcast2(wf[h]);
            acc[h][0] = ffma2(w, v.x, acc[h][0]);
            acc[h][1] = ffma2(w, v.y, acc[h][1]);
        }
    }
    float* op = g_attn + (size_t)b * 4194304 + (size_t)n * 512 + m0;
#pragma unroll
    for (int h = 0; h < 16; h++) {
        float rv = s_rb[h];
        float4 o;
        upk2(acc[h][0], o.x, o.y);
        upk2(acc[h][1], o.z, o.w);
        o.x += rv; o.y += rv; o.z += rv; o.w += rv;
        *(float4*)(op + (size_t)h * 262144) = o;
    }
}

// ---------------- attn += SCALE * q@k^T, per (b,h), 64x64 tiles ----------------
__global__ __launch_bounds__(256)
void scores_kernel()
{
    __shared__ float Qs[32][68];   // [d][n]
    __shared__ float Ks[32][68];   // [d][m]
    const int tid = threadIdx.x;
    const int bh = blockIdx.z;
    const int n0 = blockIdx.y << 6;
    const int m0 = blockIdx.x << 6;
    const float* qp = g_q + (size_t)bh * 16384;
    const float* kp = g_k + (size_t)bh * 16384;

    const int r = tid >> 2;
    const int c = (tid & 3) << 3;
    {
        float4 q1 = *(const float4*)(qp + (size_t)(n0 + r) * 32 + c);
        float4 q2 = *(const float4*)(qp + (size_t)(n0 + r) * 32 + c + 4);
        Qs[c+0][r]=q1.x; Qs[c+1][r]=q1.y; Qs[c+2][r]=q1.z; Qs[c+3][r]=q1.w;
        Qs[c+4][r]=q2.x; Qs[c+5][r]=q2.y; Qs[c+6][r]=q2.z; Qs[c+7][r]=q2.w;
        float4 k1 = *(const float4*)(kp + (size_t)(m0 + r) * 32 + c);
        float4 k2 = *(const float4*)(kp + (size_t)(m0 + r) * 32 + c + 4);
        Ks[c+0][r]=k1.x; Ks[c+1][r]=k1.y; Ks[c+2][r]=k1.z; Ks[c+3][r]=k1.w;
        Ks[c+4][r]=k2.x; Ks[c+5][r]=k2.y; Ks[c+6][r]=k2.z; Ks[c+7][r]=k2.w;
    }
    __syncthreads();

    const int tn = (tid >> 4) << 2;
    const int tm = (tid & 15) << 2;
    u64 acc[2][4];
#pragma unroll
    for (int p = 0; p < 2; p++)
#pragma unroll
        for (int j = 0; j < 4; j++) acc[p][j] = 0ull;

#pragma unroll
    for (int d = 0; d < 32; d++) {
        ulonglong2 av = *(const ulonglong2*)&Qs[d][tn];
        float4 bf = *(const float4*)&Ks[d][tm];
        u64 bb[4] = {bcast2(bf.x), bcast2(bf.y), bcast2(bf.z), bcast2(bf.w)};
        u64 ap[2] = {av.x, av.y};
#pragma unroll
        for (int p = 0; p < 2; p++)
#pragma unroll
            for (int j = 0; j < 4; j++)
                acc[p][j] = ffma2(ap[p], bb[j], acc[p][j]);
    }

#pragma unroll
    for (int p = 0; p < 2; p++) {
        float lo[4], hi[4];
#pragma unroll
        for (int j = 0; j < 4; j++) upk2(acc[p][j], lo[j], hi[j]);
#pragma unroll
        for (int rr = 0; rr < 2; rr++) {
            const float* src = rr ? hi : lo;
            float* op = g_attn + ((size_t)bh * 512 + n0 + tn + 2 * p + rr) * 512 + m0 + tm;
            float4 cur = *(float4*)op;
            cur.x += SCALE_F * src[0];
            cur.y += SCALE_F * src[1];
            cur.z += SCALE_F * src[2];
            cur.w += SCALE_F * src[3];
            *(float4*)op = cur;
        }
    }
}

// ---------------- edge path: stats + t=a+attn + expand GEMM + edge softmax wsum ----------------
__global__ __launch_bounds__(256)
void edge_kernel(const unsigned char* __restrict__ mask,
                 const float* __restrict__ ew, const float* __restrict__ eb,
                 float* __restrict__ out_edge)
{
    __shared__ float t_s[16][520];
    __shared__ float ewH[16][64];    // [h][e]
    __shared__ float eb_s[64];
    __shared__ float L_s[16];
    __shared__ unsigned char mk[512];
    const int tid = threadIdx.x;
    const int n = blockIdx.x, b = blockIdx.y;
    const int lane = tid & 31, w = tid >> 5;

    for (int i = tid; i < 1024; i += 256) { int e = i >> 4, h = i & 15; ewH[h][e] = ew[i]; }
    if (tid < 64) eb_s[tid] = eb[tid];
    mk[tid] = mask[(b << 9) + tid];
    mk[tid + 256] = mask[(b << 9) + tid + 256];

    // phase 0: load raw attn rows for this n
    const float* ap = g_attn + (size_t)b * 4194304 + (size_t)n * 512;
#pragma unroll
    for (int rep = 0; rep < 2; rep++) {
        const int mm = tid + (rep << 8);
#pragma unroll
        for (int h = 0; h < 16; h++)
            t_s[h][mm] = ap[(size_t)h * 262144 + mm];
    }
    __syncthreads();

    // phase 0b: row sums of exp (no max needed) -> L = 1/sum; warp w handles h=2w,2w+1
#pragma unroll
    for (int hh = 0; hh < 2; hh++) {
        const int h = (w << 1) + hh;
        float s = 0.f;
#pragma unroll
        for (int j = 0; j < 4; j++) {
            const int m = (lane << 2) + (j << 7);
            float4 x = *(const float4*)&t_s[h][m];
            uchar4 m4 = *(const uchar4*)&mk[m];
            if (!m4.x) s += __expf(x.x);
            if (!m4.y) s += __expf(x.y);
            if (!m4.z) s += __expf(x.z);
            if (!m4.w) s += __expf(x.w);
        }
#pragma unroll
        for (int off = 16; off > 0; off >>= 1)
            s += __shfl_xor_sync(0xffffffffu, s, off);
        if (lane == 0) {
            float inv = 1.0f / s;
            L_s[h] = inv;
            g_invden[(b * 16 + h) * 512 + n] = inv;
        }
    }
    __syncthreads();

    // phase 1: t = a + x in place
#pragma unroll
    for (int rep = 0; rep < 2; rep++) {
        const int mm = tid + (rep << 8);
        const bool k = mk[mm] != 0;
#pragma unroll
        for (int h = 0; h < 16; h++) {
            float x = t_s[h][mm];
            float a = k ? 0.f : __expf(x) * L_s[h];
            t_s[h][mm] = a + x;
        }
    }
    __syncthreads();

    // phase 2: 2 e per thread, 64 m each; weights as floats (bcast at use, low reg pressure)
    const int eg = tid >> 3;          // 0..31
    const int mg = tid & 7;           // 0..7
    const int e0 = eg << 1;
    float w0f[16], w1f[16];
#pragma unroll
    for (int h = 0; h < 16; h++) {
        w0f[h] = ewH[h][e0];
        w1f[h] = ewH[h][e0 + 1];
    }
    const u64 eba = bcast2(eb_s[e0]);
    const u64 ebb = bcast2(eb_s[e0 + 1]);
    float* gp0 = out_edge + (size_t)(b * 64 + e0) * 262144 + (size_t)n * 512;
    float* gp1 = gp0 + 262144;

    float S1a = 0.f, S2a = 0.f, S1b = 0.f, S2b = 0.f;
#pragma unroll 4
    for (int j = 0; j < 16; j++) {
        const int m0 = (mg << 2) + (j << 5);
        u64 oa0 = eba, oa1 = eba, ob0 = ebb, ob1 = ebb;
#pragma unroll
        for (int h = 0; h < 16; h++) {
            ulonglong2 tv = *(const ulonglong2*)&t_s[h][m0];
            u64 wa = bcast2(w0f[h]);
            u64 wb = bcast2(w1f[h]);
            oa0 = ffma2(wa, tv.x, oa0);
            oa1 = ffma2(wa, tv.y, oa1);
            ob0 = ffma2(wb, tv.x, ob0);
            ob1 = ffma2(wb, tv.y, ob1);
        }
        ulonglong2 sa = {oa0, oa1}, sb = {ob0, ob1};
        *(ulonglong2*)(gp0 + m0) = sa;
        *(ulonglong2*)(gp1 + m0) = sb;
        float fa[4], fb[4];
        upk2(oa0, fa[0], fa[1]); upk2(oa1, fa[2], fa[3]);
        upk2(ob0, fb[0], fb[1]); upk2(ob1, fb[2], fb[3]);
        uchar4 m4 = *(const uchar4*)&mk[m0];
        unsigned char mc[4] = {m4.x, m4.y, m4.z, m4.w};
#pragma unroll
        for (int c = 0; c < 4; c++) {
            float eva = mc[c] ? 0.f : __expf(fa[c]);
            float evb = mc[c] ? 0.f : __expf(fb[c]);
            S1a += eva; S2a = fmaf(eva, fa[c], S2a);
            S1b += evb; S2b = fmaf(evb, fb[c], S2b);
        }
    }
#pragma unroll
    for (int off = 1; off < 8; off <<= 1) {
        S1a += __shfl_xor_sync(0xffffffffu, S1a, off);
        S2a += __shfl_xor_sync(0xffffffffu, S2a, off);
        S1b += __shfl_xor_sync(0xffffffffu, S1b, off);
        S2b += __shfl_xor_sync(0xffffffffu, S2b, off);
    }
    if (mg == 0) {
        float* wr = g_wred + ((size_t)b * 512 + n) * 64;
        wr[e0]     = S2a / S1a;
        wr[e0 + 1] = S2b / S1b;
    }
}

// ---------------- node1 = a @ v per (b,h), FFMA2, no-max softmax ----------------
__global__ __launch_bounds__(256)
void node_kernel(const unsigned char* __restrict__ mask)
{
    __shared__ float a_s[64][68];
    __shared__ float v_s[64][33];
    __shared__ float Is[64];
    __shared__ unsigned char mk[512];
    const int tid = threadIdx.x;
    const int n0 = blockIdx.x << 6, h = blockIdx.y, b = blockIdx.z;
    const int bh = b * 16 + h;
    const float* ap = g_attn + (size_t)bh * 262144;
    const float* vp = g_v + (size_t)bh * 16384;
    const int d = tid & 31, nn = tid >> 5;

    if (tid < 64) Is[tid] = g_invden[bh * 512 + n0 + tid];
    for (int i = tid; i < 512; i += 256) mk[i] = mask[(b << 9) + i];
    __syncthreads();

    u64 acc2[8];
#pragma unroll
    for (int i = 0; i < 8; i++) acc2[i] = 0ull;

    for (int m0 = 0; m0 < 512; m0 += 64) {
        for (int i = tid; i < 1024; i += 256) {
            int r = i >> 4, c4 = (i & 15) << 2;
            float4 x = *(const float4*)(ap + (size_t)(n0 + r) * 512 + m0 + c4);
            float I = Is[r];
            a_s[r][c4+0] = mk[m0+c4+0] ? 0.f : __expf(x.x) * I;
            a_s[r][c4+1] = mk[m0+c4+1] ? 0.f : __expf(x.y) * I;
            a_s[r][c4+2] = mk[m0+c4+2] ? 0.f : __expf(x.z) * I;
            a_s[r][c4+3] = mk[m0+c4+3] ? 0.f : __expf(x.w) * I;
        }
        for (int i = tid; i < 512; i += 256) {
            int r = i >> 3, c4 = (i & 7) << 2;
            float4 x = *(const float4*)(vp + (size_t)(m0 + r) * 32 + c4);
            v_s[r][c4] = x.x; v_s[r][c4+1] = x.y; v_s[r][c4+2] = x.z; v_s[r][c4+3] = x.w;
        }
        __syncthreads();
#pragma unroll 4
        for (int m = 0; m < 64; m += 4) {
            u64 vp0 = pk2(v_s[m][d],   v_s[m+1][d]);
            u64 vp1 = pk2(v_s[m+2][d], v_s[m+3][d]);
#pragma unroll
            for (int i = 0; i < 8; i++) {
                ulonglong2 a2 = *(const ulonglong2*)&a_s[(nn << 3) + i][m];
                acc2[i] = ffma2(a2.x, vp0, acc2[i]);
                acc2[i] = ffma2(a2.y, vp1, acc2[i]);
            }
        }
        __syncthreads();
    }
    float* op = g_node1 + (size_t)(b * 512 + n0 + (nn << 3)) * 512 + h * 32 + d;
#pragma unroll
    for (int i = 0; i < 8; i++) {
        float lo, hi;
        upk2(acc2[i], lo, hi);
        op[(size_t)i * 512] = lo + hi;
    }
}

extern "C" void kernel_launch(void* const* d_in, const int* in_sizes, int n_in,
                              void* d_out, int out_size)
{
    const float* node_embeds = (const float*)d_in[0];
    const float* edge_embeds = (const float*)d_in[1];
    const unsigned char* padding_mask = (const unsigned char*)d_in[2];
    const float* qkv_w = (const float*)d_in[3];
    const float* qkv_b = (const float*)d_in[4];
    const float* reduce_w = (const float*)d_in[5];
    const float* reduce_b = (const float*)d_in[6];
    const float* expand_w = (const float*)d_in[7];
    const float* expand_b = (const float*)d_in[8];
    const float* fc_w = (const float*)d_in[9];
    const float* fc_b = (const float*)d_in[10];
    const float* proj_w = (const float*)d_in[11];
    const float* proj_b = (const float*)d_in[12];
    float* out = (float*)d_out;
    float* out_node = out;                 // [8,512,512]
    float* out_edge = out + 2097152;       // [8,64,512,512]

    sgemm_kernel<0><<<dim3(12, 32), 256>>>(node_embeds, qkv_w, qkv_b, nullptr, 512);
    bias_kernel<<<dim3(512, 8), 128>>>(edge_embeds, reduce_w, reduce_b);
    scores_kernel<<<dim3(8, 8, 128), 256>>>();
    edge_kernel<<<dim3(512, 8), 256>>>(padding_mask, expand_w, expand_b, out_edge);
    node_kernel<<<dim3(8, 16, 8), 256>>>(padding_mask);
    sgemm_kernel<1><<<dim3(4, 32), 256>>>(nullptr, fc_w, fc_b, nullptr, 64);
    sgemm_kernel<2><<<dim3(4, 32), 256>>>(nullptr, proj_w, proj_b, out_node, 512);
}

// round 14
// speedup vs baseline: 1.2576x; 1.0237x over previous
#include <cuda_runtime.h>
#include <cstdint>

#define SCALE_F 0.17677669529663687f

typedef unsigned long long u64;

__device__ __forceinline__ u64 pk2(float lo, float hi) {
    u64 r; asm("mov.b64 %0,{%1,%2};" : "=l"(r) : "f"(lo), "f"(hi)); return r;
}
__device__ __forceinline__ u64 bcast2(float v) { return pk2(v, v); }
__device__ __forceinline__ void upk2(u64 v, float &lo, float &hi) {
    asm("mov.b64 {%0,%1},%2;" : "=f"(lo), "=f"(hi) : "l"(v));
}
__device__ __forceinline__ u64 ffma2(u64 a, u64 b, u64 c) {
    u64 d; asm("fma.rn.f32x2 %0,%1,%2,%3;" : "=l"(d) : "l"(a), "l"(b), "l"(c)); return d;
}

// ---------------- scratch ----------------
__device__ float g_q[2097152];        // [B,H,N,D]
__device__ float g_k[2097152];
__device__ float g_v[2097152];
__device__ float g_attn[33554432];    // [B,H,N,N]
__device__ float g_invden[65536];     // [B*H*N]
__device__ float g_node1[2097152];    // [B,N,C]
__device__ float g_wred[262144];      // [B,N,E]

// ---------------- generic 128x128 SGEMM: out = A @ W^T (+bias), FFMA2 ----------------
template<int EPI>
__global__ __launch_bounds__(256)
void sgemm_kernel(const float* __restrict__ A, const float* __restrict__ W,
                  const float* __restrict__ bias, float* __restrict__ Cout, int K)
{
    __shared__ float As[8][128];
    __shared__ float Ws[8][128];
    const int tid = threadIdx.x;
    const int bm = blockIdx.y << 7;
    const int bn = blockIdx.x << 7;
    const int lr = tid >> 1;
    const int lc = (tid & 1) << 2;
    const int tm = (tid >> 4) << 3;
    const int tn = (tid & 15) << 3;

    const float* Ab = (EPI == 1) ? (const float*)g_wred
                    : (EPI == 2) ? (const float*)g_node1 : A;

    u64 acc[4][8];
#pragma unroll
    for (int p = 0; p < 4; p++)
#pragma unroll
        for (int j = 0; j < 8; j++) acc[p][j] = 0ull;

    const float* Ap = Ab + (size_t)(bm + lr) * K + lc;
    const float* Wp = W  + (size_t)(bn + lr) * K + lc;

    for (int k0 = 0; k0 < K; k0 += 8) {
        float4 av = *(const float4*)(Ap + k0);
        float4 wv = *(const float4*)(Wp + k0);
        As[lc + 0][lr] = av.x; As[lc + 1][lr] = av.y;
        As[lc + 2][lr] = av.z; As[lc + 3][lr] = av.w;
        Ws[lc + 0][lr] = wv.x; Ws[lc + 1][lr] = wv.y;
        Ws[lc + 2][lr] = wv.z; Ws[lc + 3][lr] = wv.w;
        __syncthreads();
#pragma unroll
        for (int kk = 0; kk < 8; kk++) {
            ulonglong2 a01 = *(const ulonglong2*)&As[kk][tm];
            ulonglong2 a23 = *(const ulonglong2*)&As[kk][tm + 4];
            u64 ap[4] = {a01.x, a01.y, a23.x, a23.y};
            float4 t2 = *(const float4*)&Ws[kk][tn];
            float4 t3 = *(const float4*)&Ws[kk][tn + 4];
            u64 bb[8];
            bb[0] = bcast2(t2.x); bb[1] = bcast2(t2.y);
            bb[2] = bcast2(t2.z); bb[3] = bcast2(t2.w);
            bb[4] = bcast2(t3.x); bb[5] = bcast2(t3.y);
            bb[6] = bcast2(t3.z); bb[7] = bcast2(t3.w);
#pragma unroll
            for (int p = 0; p < 4; p++)
#pragma unroll
                for (int j = 0; j < 8; j++)
                    acc[p][j] = ffma2(ap[p], bb[j], acc[p][j]);
        }
        __syncthreads();
    }

    const int col0 = bn + tn;
    float4 bv0 = *(const float4*)&bias[col0];
    float4 bv1 = *(const float4*)&bias[col0 + 4];

#pragma unroll
    for (int p = 0; p < 4; p++) {
        float v2[2][8];
#pragma unroll
        for (int j = 0; j < 8; j++) upk2(acc[p][j], v2[0][j], v2[1][j]);
#pragma unroll
        for (int rr = 0; rr < 2; rr++) {
            const int row = bm + tm + 2 * p + rr;
            float4 o0, o1;
            o0.x = v2[rr][0] + bv0.x; o0.y = v2[rr][1] + bv0.y;
            o0.z = v2[rr][2] + bv0.z; o0.w = v2[rr][3] + bv0.w;
            o1.x = v2[rr][4] + bv1.x; o1.y = v2[rr][5] + bv1.y;
            o1.z = v2[rr][6] + bv1.z; o1.w = v2[rr][7] + bv1.w;
            if (EPI == 0) {
                int s  = col0 >> 9;
                int hd = col0 & 511;
                float* base = (s == 0 ? g_q : (s == 1 ? g_k : g_v));
                int b_ = row >> 9, n = row & 511;
                float* dst = base + ((size_t)((b_ << 4) + (hd >> 5)) << 14) + (n << 5) + (hd & 31);
                *(float4*)dst = o0; *(float4*)(dst + 4) = o1;
            } else {
                float* Cb = (EPI == 1) ? (float*)g_node1 : Cout;
                float* dst = Cb + ((size_t)row << 9) + col0;
                if (EPI == 1) {
                    float4 c0 = *(const float4*)dst;
                    float4 c1 = *(const float4*)(dst + 4);
                    o0.x += c0.x; o0.y += c0.y; o0.z += c0.z; o0.w += c0.w;
                    o1.x += c1.x; o1.y += c1.y; o1.z += c1.z; o1.w += c1.w;
                }
                *(float4*)dst = o0; *(float4*)(dst + 4) = o1;
            }
        }
    }
}

// ---------------- attn = sum_e edge[b,e,n,m]*rw[h,e] + rb[h] (FFMA2, float4 w) ----------------
__global__ __launch_bounds__(128)
void bias_kernel(const float* __restrict__ edge, const float* __restrict__ rw,
                 const float* __restrict__ rb)
{
    __shared__ float rwT[64][16];   // [e][h], broadcast reads
    __shared__ float s_rb[16];
    const int tid = threadIdx.x;
    const int n = blockIdx.x, b = blockIdx.y;
    for (int i = tid; i < 1024; i += 128) { int h = i >> 6, e = i & 63; rwT[e][h] = rw[i]; }
    if (tid < 16) s_rb[tid] = rb[tid];
    __syncthreads();

    const int m0 = tid << 2;
    u64 acc[16][2];
#pragma unroll
    for (int h = 0; h < 16; h++) { acc[h][0] = 0ull; acc[h][1] = 0ull; }

    const float* ep = edge + (size_t)b * 16777216 + (size_t)n * 512 + m0;
#pragma unroll 4
    for (int e = 0; e < 64; e++) {
        ulonglong2 v = *(const ulonglong2*)(ep + (size_t)e * 262144);
        float4 w0 = *(const float4*)&rwT[e][0];
        float4 w1 = *(const float4*)&rwT[e][4];
        float4 w2 = *(const float4*)&rwT[e][8];
        float4 w3 = *(const float4*)&rwT[e][12];
        float wf[16] = {w0.x,w0.y,w0.z,w0.w, w1.x,w1.y,w1.z,w1.w,
                        w2.x,w2.y,w2.z,w2.w, w3.x,w3.y,w3.z,w3.w};
#pragma unroll
        for (int h = 0; h < 16; h++) {
            u64 w = bcast2(wf[h]);
            acc[h][0] = ffma2(w, v.x, acc[h][0]);
            acc[h][1] = ffma2(w, v.y, acc[h][1]);
        }
    }
    float* op = g_attn + (size_t)b * 4194304 + (size_t)n * 512 + m0;
#pragma unroll
    for (int h = 0; h < 16; h++) {
        float rv = s_rb[h];
        float4 o;
        upk2(acc[h][0], o.x, o.y);
        upk2(acc[h][1], o.z, o.w);
        o.x += rv; o.y += rv; o.z += rv; o.w += rv;
        *(float4*)(op + (size_t)h * 262144) = o;
    }
}

// ---------------- attn += SCALE * q@k^T, per (b,h), 64x64 tiles ----------------
__global__ __launch_bounds__(256)
void scores_kernel()
{
    __shared__ float Qs[32][68];   // [d][n]
    __shared__ float Ks[32][68];   // [d][m]
    const int tid = threadIdx.x;
    const int bh = blockIdx.z;
    const int n0 = blockIdx.y << 6;
    const int m0 = blockIdx.x << 6;
    const float* qp = g_q + (size_t)bh * 16384;
    const float* kp = g_k + (size_t)bh * 16384;

    const int r = tid >> 2;
    const int c = (tid & 3) << 3;
    {
        float4 q1 = *(const float4*)(qp + (size_t)(n0 + r) * 32 + c);
        float4 q2 = *(const float4*)(qp + (size_t)(n0 + r) * 32 + c + 4);
        Qs[c+0][r]=q1.x; Qs[c+1][r]=q1.y; Qs[c+2][r]=q1.z; Qs[c+3][r]=q1.w;
        Qs[c+4][r]=q2.x; Qs[c+5][r]=q2.y; Qs[c+6][r]=q2.z; Qs[c+7][r]=q2.w;
        float4 k1 = *(const float4*)(kp + (size_t)(m0 + r) * 32 + c);
        float4 k2 = *(const float4*)(kp + (size_t)(m0 + r) * 32 + c + 4);
        Ks[c+0][r]=k1.x; Ks[c+1][r]=k1.y; Ks[c+2][r]=k1.z; Ks[c+3][r]=k1.w;
        Ks[c+4][r]=k2.x; Ks[c+5][r]=k2.y; Ks[c+6][r]=k2.z; Ks[c+7][r]=k2.w;
    }
    __syncthreads();

    const int tn = (tid >> 4) << 2;
    const int tm = (tid & 15) << 2;
    u64 acc[2][4];
#pragma unroll
    for (int p = 0; p < 2; p++)
#pragma unroll
        for (int j = 0; j < 4; j++) acc[p][j] = 0ull;

#pragma unroll
    for (int d = 0; d < 32; d++) {
        ulonglong2 av = *(const ulonglong2*)&Qs[d][tn];
        float4 bf = *(const float4*)&Ks[d][tm];
        u64 bb[4] = {bcast2(bf.x), bcast2(bf.y), bcast2(bf.z), bcast2(bf.w)};
        u64 ap[2] = {av.x, av.y};
#pragma unroll
        for (int p = 0; p < 2; p++)
#pragma unroll
            for (int j = 0; j < 4; j++)
                acc[p][j] = ffma2(ap[p], bb[j], acc[p][j]);
    }

#pragma unroll
    for (int p = 0; p < 2; p++) {
        float lo[4], hi[4];
#pragma unroll
        for (int j = 0; j < 4; j++) upk2(acc[p][j], lo[j], hi[j]);
#pragma unroll
        for (int rr = 0; rr < 2; rr++) {
            const float* src = rr ? hi : lo;
            float* op = g_attn + ((size_t)bh * 512 + n0 + tn + 2 * p + rr) * 512 + m0 + tm;
            float4 cur = *(float4*)op;
            cur.x += SCALE_F * src[0];
            cur.y += SCALE_F * src[1];
            cur.z += SCALE_F * src[2];
            cur.w += SCALE_F * src[3];
            *(float4*)op = cur;
        }
    }
}

// ---------------- edge path: stats + t=a+attn + expand GEMM (4e/thread, volatile w) + softmax ----------------
__global__ __launch_bounds__(256)
void edge_kernel(const unsigned char* __restrict__ mask,
                 const float* __restrict__ ew, const float* __restrict__ eb,
                 float* __restrict__ out_edge)
{
    __shared__ float t_s[16][520];
    __shared__ float ewH[16][64];    // [h][e]
    __shared__ float eb_s[64];
    __shared__ float L_s[16];
    __shared__ unsigned char mk[512];
    const int tid = threadIdx.x;
    const int n = blockIdx.x, b = blockIdx.y;
    const int lane = tid & 31, w = tid >> 5;

    for (int i = tid; i < 1024; i += 256) { int e = i >> 4, h = i & 15; ewH[h][e] = ew[i]; }
    if (tid < 64) eb_s[tid] = eb[tid];
    mk[tid] = mask[(b << 9) + tid];
    mk[tid + 256] = mask[(b << 9) + tid + 256];

    // phase 0: load raw attn rows for this n
    const float* ap = g_attn + (size_t)b * 4194304 + (size_t)n * 512;
#pragma unroll
    for (int rep = 0; rep < 2; rep++) {
        const int mm = tid + (rep << 8);
#pragma unroll
        for (int h = 0; h < 16; h++)
            t_s[h][mm] = ap[(size_t)h * 262144 + mm];
    }
    __syncthreads();

    // phase 0b: row sums of exp (no max needed) -> L = 1/sum; warp w handles h=2w,2w+1
#pragma unroll
    for (int hh = 0; hh < 2; hh++) {
        const int h = (w << 1) + hh;
        float s = 0.f;
#pragma unroll
        for (int j = 0; j < 4; j++) {
            const int m = (lane << 2) + (j << 7);
            float4 x = *(const float4*)&t_s[h][m];
            uchar4 m4 = *(const uchar4*)&mk[m];
            if (!m4.x) s += __expf(x.x);
            if (!m4.y) s += __expf(x.y);
            if (!m4.z) s += __expf(x.z);
            if (!m4.w) s += __expf(x.w);
        }
#pragma unroll
        for (int off = 16; off > 0; off >>= 1)
            s += __shfl_xor_sync(0xffffffffu, s, off);
        if (lane == 0) {
            float inv = 1.0f / s;
            L_s[h] = inv;
            g_invden[(b * 16 + h) * 512 + n] = inv;
        }
    }
    __syncthreads();

    // phase 1: t = a + x in place
#pragma unroll
    for (int rep = 0; rep < 2; rep++) {
        const int mm = tid + (rep << 8);
        const bool k = mk[mm] != 0;
#pragma unroll
        for (int h = 0; h < 16; h++) {
            float x = t_s[h][mm];
            float a = k ? 0.f : __expf(x) * L_s[h];
            t_s[h][mm] = a + x;
        }
    }
    __syncthreads();

    // phase 2: 4 e per thread (16 e-groups x 16 m-groups); weights via volatile LDS.128
    const int eg = tid >> 4;          // 0..15
    const int mg = tid & 15;          // 0..15
    const int e0 = eg << 2;
    u64 bep[4];
#pragma unroll
    for (int e = 0; e < 4; e++) bep[e] = bcast2(eb_s[e0 + e]);
    float* gbase = out_edge + (size_t)(b * 64 + e0) * 262144 + (size_t)n * 512;
    const unsigned ew_addr0 = (unsigned)__cvta_generic_to_shared(&ewH[0][e0]);

    float S1[4] = {0.f, 0.f, 0.f, 0.f}, S2[4] = {0.f, 0.f, 0.f, 0.f};
    for (int j = 0; j < 8; j++) {
        const int m0 = (mg << 2) + (j << 6);
        u64 o0[4], o1[4];
#pragma unroll
        for (int e = 0; e < 4; e++) { o0[e] = bep[e]; o1[e] = bep[e]; }
        unsigned ew_addr = ew_addr0;
#pragma unroll
        for (int h = 0; h < 16; h++) {
            ulonglong2 tv = *(const ulonglong2*)&t_s[h][m0];
            float wx, wy, wz, ww;
            asm volatile("ld.shared.v4.f32 {%0,%1,%2,%3},[%4];"
                : "=f"(wx), "=f"(wy), "=f"(wz), "=f"(ww) : "r"(ew_addr));
            ew_addr += 256;   // 64 floats row stride
            u64 w0 = bcast2(wx), w1 = bcast2(wy), w2 = bcast2(wz), w3 = bcast2(ww);
            o0[0] = ffma2(w0, tv.x, o0[0]); o1[0] = ffma2(w0, tv.y, o1[0]);
            o0[1] = ffma2(w1, tv.x, o0[1]); o1[1] = ffma2(w1, tv.y, o1[1]);
            o0[2] = ffma2(w2, tv.x, o0[2]); o1[2] = ffma2(w2, tv.y, o1[2]);
            o0[3] = ffma2(w3, tv.x, o0[3]); o1[3] = ffma2(w3, tv.y, o1[3]);
        }
        uchar4 m4 = *(const uchar4*)&mk[m0];
        unsigned char mc[4] = {m4.x, m4.y, m4.z, m4.w};
#pragma unroll
        for (int e = 0; e < 4; e++) {
            ulonglong2 st; st.x = o0[e]; st.y = o1[e];
            *(ulonglong2*)(gbase + (size_t)e * 262144 + m0) = st;
            float f[4];
            upk2(o0[e], f[0], f[1]);
            upk2(o1[e], f[2], f[3]);
#pragma unroll
            for (int c = 0; c < 4; c++) {
                float ev = mc[c] ? 0.f : __expf(f[c]);
                S1[e] += ev;
                S2[e] = fmaf(ev, f[c], S2[e]);
            }
        }
    }
#pragma unroll
    for (int off = 1; off < 16; off <<= 1) {
#pragma unroll
        for (int e = 0; e < 4; e++) {
            S1[e] += __shfl_xor_sync(0xffffffffu, S1[e], off);
            S2[e] += __shfl_xor_sync(0xffffffffu, S2[e], off);
        }
    }
    if (mg == 0) {
        float* wr = g_wred + ((size_t)b * 512 + n) * 64 + e0;
#pragma unroll
        for (int e = 0; e < 4; e++) wr[e] = S2[e] / S1[e];
    }
}

// ---------------- node1 = a @ v per (b,h), FFMA2, no-max softmax ----------------
__global__ __launch_bounds__(256)
void node_kernel(const unsigned char* __restrict__ mask)
{
    __shared__ float a_s[64][68];
    __shared__ float v_s[64][33];
    __shared__ float Is[64];
    __shared__ unsigned char mk[512];
    const int tid = threadIdx.x;
    const int n0 = blockIdx.x << 6, h = blockIdx.y, b = blockIdx.z;
    const int bh = b * 16 + h;
    const float* ap = g_attn + (size_t)bh * 262144;
    const float* vp = g_v + (size_t)bh * 16384;
    const int d = tid & 31, nn = tid >> 5;

    if (tid < 64) Is[tid] = g_invden[bh * 512 + n0 + tid];
    for (int i = tid; i < 512; i += 256) mk[i] = mask[(b << 9) + i];
    __syncthreads();

    u64 acc2[8];
#pragma unroll
    for (int i = 0; i < 8; i++) acc2[i] = 0ull;

    for (int m0 = 0; m0 < 512; m0 += 64) {
        for (int i = tid; i < 1024; i += 256) {
            int r = i >> 4, c4 = (i & 15) << 2;
            float4 x = *(const float4*)(ap + (size_t)(n0 + r) * 512 + m0 + c4);
            float I = Is[r];
            a_s[r][c4+0] = mk[m0+c4+0] ? 0.f : __expf(x.x) * I;
            a_s[r][c4+1] = mk[m0+c4+1] ? 0.f : __expf(x.y) * I;
            a_s[r][c4+2] = mk[m0+c4+2] ? 0.f : __expf(x.z) * I;
            a_s[r][c4+3] = mk[m0+c4+3] ? 0.f : __expf(x.w) * I;
        }
        for (int i = tid; i < 512; i += 256) {
            int r = i >> 3, c4 = (i & 7) << 2;
            float4 x = *(const float4*)(vp + (size_t)(m0 + r) * 32 + c4);
            v_s[r][c4] = x.x; v_s[r][c4+1] = x.y; v_s[r][c4+2] = x.z; v_s[r][c4+3] = x.w;
        }
        __syncthreads();
#pragma unroll 4
        for (int m = 0; m < 64; m += 4) {
            u64 vp0 = pk2(v_s[m][d],   v_s[m+1][d]);
            u64 vp1 = pk2(v_s[m+2][d], v_s[m+3][d]);
#pragma unroll
            for (int i = 0; i < 8; i++) {
                ulonglong2 a2 = *(const ulonglong2*)&a_s[(nn << 3) + i][m];
                acc2[i] = ffma2(a2.x, vp0, acc2[i]);
                acc2[i] = ffma2(a2.y, vp1, acc2[i]);
            }
        }
        __syncthreads();
    }
    float* op = g_node1 + (size_t)(b * 512 + n0 + (nn << 3)) * 512 + h * 32 + d;
#pragma unroll
    for (int i = 0; i < 8; i++) {
        float lo, hi;
        upk2(acc2[i], lo, hi);
        op[(size_t)i * 512] = lo + hi;
    }
}

extern "C" void kernel_launch(void* const* d_in, const int* in_sizes, int n_in,
                              void* d_out, int out_size)
{
    const float* node_embeds = (const float*)d_in[0];
    const float* edge_embeds = (const float*)d_in[1];
    const unsigned char* padding_mask = (const unsigned char*)d_in[2];
    const float* qkv_w = (const float*)d_in[3];
    const float* qkv_b = (const float*)d_in[4];
    const float* reduce_w = (const float*)d_in[5];
    const float* reduce_b = (const float*)d_in[6];
    const float* expand_w = (const float*)d_in[7];
    const float* expand_b = (const float*)d_in[8];
    const float* fc_w = (const float*)d_in[9];
    const float* fc_b = (const float*)d_in[10];
    const float* proj_w = (const float*)d_in[11];
    const float* proj_b = (const float*)d_in[12];
    float* out = (float*)d_out;
    float* out_node = out;                 // [8,512,512]
    float* out_edge = out + 2097152;       // [8,64,512,512]

    sgemm_kernel<0><<<dim3(12, 32), 256>>>(node_embeds, qkv_w, qkv_b, nullptr, 512);
    bias_kernel<<<dim3(512, 8), 128>>>(edge_embeds, reduce_w, reduce_b);
    scores_kernel<<<dim3(8, 8, 128), 256>>>();
    edge_kernel<<<dim3(512, 8), 256>>>(padding_mask, expand_w, expand_b, out_edge);
    node_kernel<<<dim3(8, 16, 8), 256>>>(padding_mask);
    sgemm_kernel<1><<<dim3(4, 32), 256>>>(nullptr, fc_w, fc_b, nullptr, 64);
    sgemm_kernel<2><<<dim3(4, 32), 256>>>(nullptr, proj_w, proj_b, out_node, 512);
}